// round 6
// baseline (speedup 1.0000x reference)
#include <cuda_runtime.h>

// ---------------------------------------------------------------------------
// RNN_70480413327462: 59-step patch-grid RNN + 9-neighbor center attention.
// R5: 4-warp teams (8-row weight amortization, 1-wf weight loads),
// contiguous triple-block K/V gathers, L1-cached gathers (fence invalidates).
// ---------------------------------------------------------------------------

#define NBLK   148
#define NTHR   896
#define NTEAMS 7
#define PP     4096
#define NROWS  8192
#define HH     32
#define TSTEPS 59
#define NOBS   10
#define KPAD   36
#define PPK    (PP * KPAD)
#define RBS    27                         // float4 stride of RB row (108 words, %32=12)
#define INV_SQRT_E 0.1714985851425088f    // 1/sqrt(34)

__device__ float g_Q[2][NROWS * KPAD];
__device__ float g_K[2][NROWS * KPAD];
__device__ float g_V[2][NROWS * KPAD];
__device__ unsigned g_arrive = 0;
__device__ volatile unsigned g_gen = 0;

struct Smem {
    float4 Wc[32][17];        // RNN: c<8 W_x2h chunk c, c>=8 W_h2h chunk c-8
    float4 Wq[32][9];
    float4 Wk[32][9];
    float4 Wv[32][9];
    float4 Mw[32][9];         // (W_fcsa@W_out)^T chunks over f (9 used)
    float4 Wf[32][9];         // W_fc2 chunks (8 used)
    float4 We[6][9];          // ext rows (q32,q33,k32,k33,v32,v33)
    // RB row layout (float4 idx): [0..8] inp/pred/o (36f), [9..16] h, [17..24] ht
    float4 RB[NTEAMS][8][RBS];
    unsigned sbase;
};

__device__ __forceinline__ float warpAllSum(float v) {
#pragma unroll
    for (int o = 16; o > 0; o >>= 1) v += __shfl_xor_sync(0xffffffffu, v, o);
    return v;
}

__device__ __forceinline__ float ftanh(float x) {
    float e = __expf(2.f * x);
    return 1.f - __fdividef(2.f, e + 1.f);
}

__device__ __forceinline__ float dot4(float4 a, float4 b) {
    return fmaf(a.x, b.x, fmaf(a.y, b.y, fmaf(a.z, b.z, a.w * b.w)));
}

extern __shared__ unsigned char smem_raw[];

__global__ void __launch_bounds__(NTHR, 1) rnn_kernel(
    const float* __restrict__ x,
    const float* __restrict__ W_x2h, const float* __restrict__ b_x2h,
    const float* __restrict__ W_h2h, const float* __restrict__ b_h2h,
    const float* __restrict__ W_fc2, const float* __restrict__ b_fc2,
    const float* __restrict__ ln_g,  const float* __restrict__ ln_b,
    const float* __restrict__ W_fcsa,const float* __restrict__ b_fcsa,
    const float* __restrict__ W_in,  const float* __restrict__ b_in,
    const float* __restrict__ W_out, const float* __restrict__ b_out,
    float* __restrict__ out)
{
    Smem* sm = reinterpret_cast<Smem*>(smem_raw);
    const int tid = threadIdx.x;

    // ---------------- smem weight init ----------------
    for (int idx = tid; idx < 32 * 16; idx += NTHR) {
        int e = idx >> 4, c = idx & 15;
        const float* src = (c < 8) ? (W_x2h + e * 32 + c * 4)
                                   : (W_h2h + e * 32 + (c - 8) * 4);
        sm->Wc[e][c] = make_float4(src[0], src[1], src[2], src[3]);
    }
    for (int idx = tid; idx < 32 * 8; idx += NTHR) {
        int e = idx >> 3, c = idx & 7, i = c * 4;
        const float* q = W_in + e * 34 + i;
        const float* k = W_in + (34 + e) * 34 + i;
        const float* v = W_in + (68 + e) * 34 + i;
        const float* f = W_fc2 + e * 32 + i;
        sm->Wq[e][c] = make_float4(q[0], q[1], q[2], q[3]);
        sm->Wk[e][c] = make_float4(k[0], k[1], k[2], k[3]);
        sm->Wv[e][c] = make_float4(v[0], v[1], v[2], v[3]);
        sm->Wf[e][c] = make_float4(f[0], f[1], f[2], f[3]);
    }
    for (int idx = tid; idx < 32 * 9; idx += NTHR) {
        int e = idx / 9, c = idx % 9;
        float w[4];
#pragma unroll
        for (int d = 0; d < 4; d++) {
            int f = c * 4 + d;
            float acc = 0.f;
            if (f < 34)
                for (int g = 0; g < 34; g++)
                    acc += W_fcsa[e * 34 + g] * W_out[g * 34 + f];
            w[d] = acc;
        }
        sm->Mw[e][c] = make_float4(w[0], w[1], w[2], w[3]);
    }
    for (int idx = tid; idx < 6 * 8; idx += NTHR) {
        int j = idx >> 3, c = idx & 7;
        int row = (j >> 1) * 34 + 32 + (j & 1);
        const float* src = W_in + row * 34 + c * 4;
        sm->We[j][c] = make_float4(src[0], src[1], src[2], src[3]);
    }
    // zero RB (h init = 0)
    for (int idx = tid; idx < NTEAMS * 8 * RBS; idx += NTHR)
        sm->RB[0][0][idx] = make_float4(0.f, 0.f, 0.f, 0.f);
    if (tid == 0) sm->sbase = g_gen;

    const int lane  = tid & 31;
    const int wid   = tid >> 5;
    const int team  = wid >> 2;
    const int wT    = wid & 3;            // warp-in-team
    const int barId = team + 1;           // named barriers 1..7
    const int teamG = blockIdx.x * NTEAMS + team;
    const int pBase = teamG * 4;
    const bool active = (pBase < PP);

    const int el  = lane & 7;
    const int rg  = lane >> 3;
    const int eMy = wT * 8 + el;          // output element owned in split GEMVs
    const int r0  = rg;                   // team rows handled by this lane
    const int r1  = rg + 4;
    const int pi0 = rg >> 1;              // patch idx of r0
    const int pi1 = pi0 + 2;              // patch idx of r1
    const int fr0 = wT * 2;               // rows owned for fc2/x/out (patch wT, b=0/1)
    const int fr1 = fr0 + 1;
    const int ownP = pBase + wT;          // this warp's attention patch

    const int lane9 = lane % 9;
    const int mli   = (lane < 27) ? lane / 9 : 0;

    // ---------------- per-lane constants ----------------
    float bcomb=0.f, bb=0.f, bf=0.f, lng=0.f, lnb=0.f;
    float bqA=0.f,bkA=0.f,bvA=0.f, bqB=0.f,bkB=0.f,bvB=0.f;
    float exC = 0.f;
    int eoffG = 0;
    int pqMine = 0, nbBase = 0;
    int qkOff0 = 0, qkOff1 = 0, growF0 = 0, growF1 = 0;
    const int  exJ   = lane % 6;
    const bool exAct = (lane < 12);
    const int  rExt  = fr0 + ((lane >= 6) ? 1 : 0);

    if (active) {
#pragma unroll
        for (int ps = 0; ps < 2; ps++) {
            int p = pBase + (ps ? pi1 : pi0);
            float c0 = (float)(p >> 6) * (1.f / 64.f);
            float c1 = (float)(p & 63) * (1.f / 64.f);
            float bq = b_in[eMy]      + c0 * W_in[eMy * 34 + 32]        + c1 * W_in[eMy * 34 + 33];
            float bk = b_in[34 + eMy] + c0 * W_in[(34 + eMy) * 34 + 32] + c1 * W_in[(34 + eMy) * 34 + 33];
            float bv = b_in[68 + eMy] + c0 * W_in[(68 + eMy) * 34 + 32] + c1 * W_in[(68 + eMy) * 34 + 33];
            if (ps) { bqB = bq; bkB = bk; bvB = bv; }
            else    { bqA = bq; bkA = bk; bvA = bv; }
        }
        {   // attention geometry for own patch
            int r = ownP >> 6, cI = ownP & 63;
            int rc  = min(max(r, 1), 62);
            int ccn = min(max(cI, 1), 62);
            pqMine = (rc * 64 + ccn) * KPAD;
            nbBase = ((rc - 1) * 64 + (ccn - 1)) * KPAD;
        }
        bcomb = b_x2h[eMy] + b_h2h[eMy];
        {
            float acc = b_fcsa[eMy];
            for (int g = 0; g < 34; g++) acc += b_out[g] * W_fcsa[eMy * 34 + g];
            bb = acc;
        }
        bf  = b_fc2[lane];
        lng = ln_g[lane];
        lnb = ln_b[lane];
        if (exAct) {
            int extrow = (exJ >> 1) * 34 + 32 + (exJ & 1);
            float c0 = (float)(ownP >> 6) * (1.f / 64.f);
            float c1 = (float)(ownP & 63) * (1.f / 64.f);
            exC = b_in[extrow] + c0 * W_in[extrow * 34 + 32] + c1 * W_in[extrow * 34 + 33];
            eoffG = ((rExt & 1) * PP + ownP) * KPAD + 32 + (exJ & 1);
        }
        qkOff0 = ((r0 & 1) * PP + pBase + pi0) * KPAD;
        qkOff1 = ((r1 & 1) * PP + pBase + pi1) * KPAD;
        growF0 = ownP;            // (fr0: b=0)
        growF1 = PP + ownP;       // (fr1: b=1)

        // zero pads (elements 34,35) of this warp's fc2 rows, both buffers
        if (lane < 2) {
#pragma unroll
            for (int par = 0; par < 2; par++) {
                size_t oA = (size_t)growF0 * KPAD + 34 + lane;
                size_t oB = (size_t)growF1 * KPAD + 34 + lane;
                g_Q[par][oA] = 0.f; g_K[par][oA] = 0.f; g_V[par][oA] = 0.f;
                g_Q[par][oB] = 0.f; g_K[par][oB] = 0.f; g_V[par][oB] = 0.f;
            }
        }
    }
    __syncthreads();
    const unsigned sbase = sm->sbase;

    float4* RB0  = sm->RB[team][r0];
    float4* RB1  = sm->RB[team][r1];
    float*  RB0f = (float*)RB0;
    float*  RB1f = (float*)RB1;
    float4* RF0  = sm->RB[team][fr0];
    float4* RF1  = sm->RB[team][fr1];
    float*  RF0f = (float*)RF0;
    float*  RF1f = (float*)RF1;
    float4* REx  = sm->RB[team][rExt];

    float ht0 = 0.f, ht1 = 0.f;

#define TBAR() asm volatile("bar.sync %0, 128;" :: "r"(barId) : "memory")

    for (int t = 0; t < TSTEPS; t++) {
        const int buf = t & 1;
        float* Qb = g_Q[buf];
        float* Kb = g_K[buf];
        float* Vb = g_V[buf];

        // =============== PHASE 1 ===============
        if (active) {
            if (t < NOBS) {   // stage x for owned rows (chunks 0..7)
                const float* xb = x + (size_t)t * NROWS * HH;
                RF0f[lane] = xb[(size_t)growF0 * HH + lane];
                RF1f[lane] = xb[(size_t)growF1 * HH + lane];
            }
            TBAR();   // A: inputs staged

            // --- RNN GEMV (8-way output-split, rows r0,r1) ---
            float a0 = bcomb, a1 = bcomb;
#pragma unroll
            for (int c = 0; c < 16; c++) {
                float4 w = sm->Wc[eMy][c];
                int dc = (c < 8) ? c : c + 1;   // h at chunks 9..16
                a0 += dot4(RB0[dc], w);
                a1 += dot4(RB1[dc], w);
            }
            ht0 = ftanh(a0);
            ht1 = ftanh(a1);
            RB0f[68 + eMy] = ht0;   // ht at chunks 17..24 (no overwrite race)
            RB1f[68 + eMy] = ht1;
            TBAR();   // B: ht staged

            // --- QKV GEMV (reads ht chunks 17..24) ---
            float q0=bqA,k0=bkA,v0=bvA, q1=bqB,k1=bkB,v1=bvB;
#pragma unroll
            for (int c = 0; c < 8; c++) {
                float4 wq = sm->Wq[eMy][c];
                float4 wk = sm->Wk[eMy][c];
                float4 wv = sm->Wv[eMy][c];
                float4 t0 = RB0[17 + c];
                float4 t1 = RB1[17 + c];
                q0 += dot4(t0, wq); k0 += dot4(t0, wk); v0 += dot4(t0, wv);
                q1 += dot4(t1, wq); k1 += dot4(t1, wk); v1 += dot4(t1, wv);
            }
            Qb[qkOff0 + eMy] = q0; Kb[qkOff0 + eMy] = k0; Vb[qkOff0 + eMy] = v0;
            Qb[qkOff1 + eMy] = q1; Kb[qkOff1 + eMy] = k1; Vb[qkOff1 + eMy] = v1;

            // --- ext elements e=32,33 for own patch rows ---
            if (exAct) {
                float ex = exC;
#pragma unroll
                for (int c = 0; c < 8; c++)
                    ex += dot4(REx[17 + c], sm->We[exJ][c]);
                float* eb = (exJ < 2) ? Qb : ((exJ < 4) ? Kb : Vb);
                eb[eoffG] = ex;
            }
        }

        // =============== GRID BARRIER ===============
        {
            __threadfence();
            __syncthreads();
            if (tid == 0) {
                unsigned want = sbase + (unsigned)t + 1u;
                unsigned tk = atomicAdd(&g_arrive, 1u);
                if ((tk % (unsigned)NBLK) == (unsigned)(NBLK - 1)) {
                    g_gen = want;
                } else {
                    while ((int)(g_gen - want) < 0) __nanosleep(32);
                }
            }
            __syncthreads();
            __threadfence();   // gpu-scope fence: also invalidates L1 (CCTL.IVALL)
        }

        // =============== PHASE 2 ===============
        if (active) {
#pragma unroll
            for (int b = 0; b < 2; b++) {
                const int bAdd = b * PPK;
                // q chunk for this lane's (m, chunk) role
                float4 qv = ((const float4*)(Qb + pqMine + bAdd))[lane9];
                // 3 contiguous triple-blocks of K (rows nb 3t..3t+2), lane-linear
                float s0, s1, s2;
#pragma unroll
                for (int tb = 0; tb < 3; tb++) {
                    float p = 0.f;
                    if (lane < 27) {
                        float4 kb = ((const float4*)(Kb + nbBase + tb * (64 * KPAD) + bAdd))[lane];
                        p = dot4(kb, qv);
                    }
                    float ts = p + __shfl_down_sync(0xffffffffu, p, 1);
                    ts += __shfl_down_sync(0xffffffffu, ts, 2);
                    ts += __shfl_down_sync(0xffffffffu, ts, 4);
                    ts += __shfl_down_sync(0xffffffffu, p, 8);   // sum of 9 at leaders 0,9,18
                    if (tb == 0) s0 = ts; else if (tb == 1) s1 = ts; else s2 = ts;
                }
                float sv[9];
#pragma unroll
                for (int m = 0; m < 9; m++) {
                    float src = (m < 3) ? s0 : ((m < 6) ? s1 : s2);
                    sv[m] = __shfl_sync(0xffffffffu, src, 9 * (m % 3));
                }
                float mx = sv[0];
#pragma unroll
                for (int m = 1; m < 9; m++) mx = fmaxf(mx, sv[m]);
                float ssum = 0.f;
#pragma unroll
                for (int m = 0; m < 9; m++) {
                    sv[m] = __expf((sv[m] - mx) * INV_SQRT_E);
                    ssum += sv[m];
                }
                float inv = __fdividef(1.f, ssum);
#pragma unroll
                for (int m = 0; m < 9; m++) sv[m] *= inv;

                // V mix via triple-blocks: lane holds (m = 3tb+mli, chunk lane%9)
                float4 po = make_float4(0.f, 0.f, 0.f, 0.f);
#pragma unroll
                for (int tb = 0; tb < 3; tb++) {
                    float4 vb = make_float4(0.f, 0.f, 0.f, 0.f);
                    if (lane < 27)
                        vb = ((const float4*)(Vb + nbBase + tb * (64 * KPAD) + bAdd))[lane];
                    float wm = (mli == 0) ? sv[3 * tb]
                             : ((mli == 1) ? sv[3 * tb + 1] : sv[3 * tb + 2]);
                    po.x = fmaf(wm, vb.x, po.x);
                    po.y = fmaf(wm, vb.y, po.y);
                    po.z = fmaf(wm, vb.z, po.z);
                    po.w = fmaf(wm, vb.w, po.w);
                }
                float4 o4;
                o4.x = po.x + __shfl_sync(0xffffffffu, po.x, (lane + 9) & 31)
                            + __shfl_sync(0xffffffffu, po.x, (lane + 18) & 31);
                o4.y = po.y + __shfl_sync(0xffffffffu, po.y, (lane + 9) & 31)
                            + __shfl_sync(0xffffffffu, po.y, (lane + 18) & 31);
                o4.z = po.z + __shfl_sync(0xffffffffu, po.z, (lane + 9) & 31)
                            + __shfl_sync(0xffffffffu, po.z, (lane + 18) & 31);
                o4.w = po.w + __shfl_sync(0xffffffffu, po.w, (lane + 9) & 31)
                            + __shfl_sync(0xffffffffu, po.w, (lane + 18) & 31);
                if (lane < 9)
                    sm->RB[team][fr0 + b][lane] = o4;   // o chunks 0..8
            }
            TBAR();   // C: o staged

            // --- fused out-proj + fcsa (output-split) ---
            float d0 = bb, d1 = bb;
#pragma unroll
            for (int c = 0; c < 9; c++) {
                float4 wm4 = sm->Mw[eMy][c];
                d0 += dot4(RB0[c], wm4);
                d1 += dot4(RB1[c], wm4);
            }
            float h0 = ht0 + d0;
            float h1 = ht1 + d1;
            RB0f[36 + eMy] = h0;    // h chunks 9..16
            RB1f[36 + eMy] = h1;
            TBAR();   // D: h staged

            // --- fc2 + LN for owned rows (lane = e, full row) ---
            float y0 = bf, y1 = bf;
#pragma unroll
            for (int c = 0; c < 8; c++) {
                float4 wf = sm->Wf[lane][c];
                y0 += dot4(RF0[9 + c], wf);
                y1 += dot4(RF1[9 + c], wf);
            }
            float m0 = warpAllSum(y0) * (1.f / 32.f);
            float dd0 = y0 - m0;
            float var0 = warpAllSum(dd0 * dd0) * (1.f / 32.f);
            float pred0 = dd0 * rsqrtf(var0 + 1e-5f) * lng + lnb;
            float m1 = warpAllSum(y1) * (1.f / 32.f);
            float dd1 = y1 - m1;
            float var1 = warpAllSum(dd1 * dd1) * (1.f / 32.f);
            float pred1 = dd1 * rsqrtf(var1 + 1e-5f) * lng + lnb;

            RF0f[lane] = pred0;     // stage as next-step input (chunks 0..7)
            RF1f[lane] = pred1;

            float* ob = out + (size_t)t * NROWS * HH;
            ob[(size_t)growF0 * HH + lane] = pred0;
            ob[(size_t)growF1 * HH + lane] = pred1;
        }
    }
#undef TBAR
}

extern "C" void kernel_launch(void* const* d_in, const int* in_sizes, int n_in,
                              void* d_out, int out_size) {
    (void)in_sizes; (void)n_in; (void)out_size;
    cudaFuncSetAttribute(rnn_kernel, cudaFuncAttributeMaxDynamicSharedMemorySize,
                         (int)sizeof(Smem));
    rnn_kernel<<<NBLK, NTHR, sizeof(Smem)>>>(
        (const float*)d_in[0],
        (const float*)d_in[1],  (const float*)d_in[2],
        (const float*)d_in[3],  (const float*)d_in[4],
        (const float*)d_in[5],  (const float*)d_in[6],
        (const float*)d_in[7],  (const float*)d_in[8],
        (const float*)d_in[9],  (const float*)d_in[10],
        (const float*)d_in[11], (const float*)d_in[12],
        (const float*)d_in[13], (const float*)d_in[14],
        (float*)d_out);
}